// round 1
// baseline (speedup 1.0000x reference)
#include <cuda_runtime.h>
#include <math.h>

// Problem constants
#define KB   8        // batch
#define KS   2048     // sequence
#define KD   512      // d_in == d_out
#define KM   (KB*KS)  // 16384 total rows

// Scratch (device globals — no allocations allowed)
__device__ float g_q[(size_t)KM * KD];
__device__ float g_k[(size_t)KM * KD];
__device__ float g_v[(size_t)KM * KD];
__device__ float g_s[(size_t)KB * KS * KS];

// Tiled GEMM config: 128x128 block tile, K-step 8, 256 threads, 8x8 per thread
#define BM 128
#define BN 128
#define BKK 8
#define TM 8
#define TN 8
#define NTHR 256

__device__ __forceinline__ float block_scale() { return 0.044194173824159216f; } // 1/sqrt(512)

// MODE 0: C = A[M,K] * B[K,N] + bias[N]                 (projections)
// MODE 1: C = (A[M,K] * B^T  (B is [N,K])) * scale + mask[M,N]   (scores)
// MODE 2: C = A[M,K] * B[K,N]                            (attn @ V)
template<int MODE>
__global__ __launch_bounds__(NTHR)
void gemm_kernel(const float* __restrict__ A,
                 const float* __restrict__ Bm,
                 const float* __restrict__ aux,
                 float* __restrict__ C,
                 int M, int N, int K,
                 size_t strideA, size_t strideB, size_t strideC, size_t strideAux)
{
    __shared__ float As[BKK][BM];
    __shared__ float Bs[BKK][BN];

    A   += strideA   * (size_t)blockIdx.z;
    Bm  += strideB   * (size_t)blockIdx.z;
    C   += strideC   * (size_t)blockIdx.z;
    aux += strideAux * (size_t)blockIdx.z;

    const int t  = threadIdx.x;
    const int tx = t & 15;        // 16 threads across N
    const int ty = t >> 4;        // 16 threads across M
    const int bm = blockIdx.y * BM;
    const int bn = blockIdx.x * BN;

    // A-tile loader indices: 128 rows x 8 cols -> 256 float4 loads
    const int arow = t >> 1;            // 0..127
    const int acol = (t & 1) * 4;       // 0 or 4
    // B-tile loader (NN): 8 rows x 128 cols -> 256 float4 loads
    const int brow = t >> 5;            // 0..7
    const int bcol = (t & 31) * 4;      // 0..124

    float acc[TM][TN];
    #pragma unroll
    for (int i = 0; i < TM; ++i)
        #pragma unroll
        for (int j = 0; j < TN; ++j)
            acc[i][j] = 0.0f;

    for (int k0 = 0; k0 < K; k0 += BKK) {
        // Load A tile (row-major [M,K], ld = K), store transposed into smem
        {
            float4 av = *reinterpret_cast<const float4*>(
                &A[(size_t)(bm + arow) * K + (k0 + acol)]);
            As[acol + 0][arow] = av.x;
            As[acol + 1][arow] = av.y;
            As[acol + 2][arow] = av.z;
            As[acol + 3][arow] = av.w;
        }
        if (MODE == 1) {
            // B is [N,K] row-major; Bs[kk][n] = Bm[(bn+n)*K + k0+kk]
            float4 bv = *reinterpret_cast<const float4*>(
                &Bm[(size_t)(bn + arow) * K + (k0 + acol)]);
            Bs[acol + 0][arow] = bv.x;
            Bs[acol + 1][arow] = bv.y;
            Bs[acol + 2][arow] = bv.z;
            Bs[acol + 3][arow] = bv.w;
        } else {
            // B is [K,N] row-major, ld = N
            float4 bv = *reinterpret_cast<const float4*>(
                &Bm[(size_t)(k0 + brow) * N + (bn + bcol)]);
            *reinterpret_cast<float4*>(&Bs[brow][bcol]) = bv;
        }
        __syncthreads();

        #pragma unroll
        for (int kk = 0; kk < BKK; ++kk) {
            float a[TM], b[TN];
            *reinterpret_cast<float4*>(&a[0]) =
                *reinterpret_cast<const float4*>(&As[kk][ty * TM + 0]);
            *reinterpret_cast<float4*>(&a[4]) =
                *reinterpret_cast<const float4*>(&As[kk][ty * TM + 4]);
            *reinterpret_cast<float4*>(&b[0]) =
                *reinterpret_cast<const float4*>(&Bs[kk][tx * TN + 0]);
            *reinterpret_cast<float4*>(&b[4]) =
                *reinterpret_cast<const float4*>(&Bs[kk][tx * TN + 4]);
            #pragma unroll
            for (int i = 0; i < TM; ++i)
                #pragma unroll
                for (int j = 0; j < TN; ++j)
                    acc[i][j] = fmaf(a[i], b[j], acc[i][j]);
        }
        __syncthreads();
    }

    // Epilogue
    #pragma unroll
    for (int i = 0; i < TM; ++i) {
        const int r = bm + ty * TM + i;
        #pragma unroll
        for (int j = 0; j < TN; ++j) {
            const int c = bn + tx * TN + j;
            float v = acc[i][j];
            if (MODE == 0) v += aux[c];
            if (MODE == 1) v = v * block_scale() + aux[(size_t)r * N + c];
            C[(size_t)r * N + c] = v;
        }
    }
}

// Row softmax over 2048 elements, one block per row, row cached in smem.
__global__ __launch_bounds__(256)
void softmax_kernel(float* __restrict__ S)
{
    __shared__ float buf[KS];      // 8 KB
    __shared__ float red[8];

    float* p = S + (size_t)blockIdx.x * KS;
    const int t    = threadIdx.x;
    const int lane = t & 31;
    const int wid  = t >> 5;

    float mx = -3.4e38f;
    #pragma unroll
    for (int i = t; i < KS; i += 256) {
        float v = p[i];
        buf[i] = v;
        mx = fmaxf(mx, v);
    }
    #pragma unroll
    for (int o = 16; o > 0; o >>= 1)
        mx = fmaxf(mx, __shfl_xor_sync(0xffffffffu, mx, o));
    if (lane == 0) red[wid] = mx;
    __syncthreads();
    mx = fmaxf(fmaxf(fmaxf(red[0], red[1]), fmaxf(red[2], red[3])),
               fmaxf(fmaxf(red[4], red[5]), fmaxf(red[6], red[7])));
    __syncthreads();   // everyone done reading red before reuse

    float sum = 0.0f;
    #pragma unroll
    for (int i = t; i < KS; i += 256) {
        float e = __expf(buf[i] - mx);
        buf[i] = e;
        sum += e;
    }
    #pragma unroll
    for (int o = 16; o > 0; o >>= 1)
        sum += __shfl_xor_sync(0xffffffffu, sum, o);
    if (lane == 0) red[wid] = sum;
    __syncthreads();
    sum = ((red[0] + red[1]) + (red[2] + red[3])) +
          ((red[4] + red[5]) + (red[6] + red[7]));
    const float inv = 1.0f / sum;

    #pragma unroll
    for (int i = t; i < KS; i += 256)
        p[i] = buf[i] * inv;
}

extern "C" void kernel_launch(void* const* d_in, const int* in_sizes, int n_in,
                              void* d_out, int out_size)
{
    (void)in_sizes; (void)n_in; (void)out_size;
    const float* Q    = (const float*)d_in[0];
    const float* K    = (const float*)d_in[1];
    const float* V    = (const float*)d_in[2];
    const float* mask = (const float*)d_in[3];
    const float* Wq   = (const float*)d_in[4];
    const float* bq   = (const float*)d_in[5];
    const float* Wk   = (const float*)d_in[6];
    const float* bk   = (const float*)d_in[7];
    const float* Wv   = (const float*)d_in[8];
    const float* bv   = (const float*)d_in[9];
    float* out = (float*)d_out;

    float *q, *k, *v, *s;
    cudaGetSymbolAddress((void**)&q, g_q);
    cudaGetSymbolAddress((void**)&k, g_k);
    cudaGetSymbolAddress((void**)&v, g_v);
    cudaGetSymbolAddress((void**)&s, g_s);

    dim3 tpb(NTHR);

    // QKV projections: M=16384, N=512, K=512
    dim3 gp(KD / BN, KM / BM, 1);
    gemm_kernel<0><<<gp, tpb>>>(Q, Wq, bq, q, KM, KD, KD, 0, 0, 0, 0);
    gemm_kernel<0><<<gp, tpb>>>(K, Wk, bk, k, KM, KD, KD, 0, 0, 0, 0);
    gemm_kernel<0><<<gp, tpb>>>(V, Wv, bv, v, KM, KD, KD, 0, 0, 0, 0);

    // Scores: per batch S x S, K=512; C = q k^T * scale + mask
    dim3 gs(KS / BN, KS / BM, KB);
    gemm_kernel<1><<<gs, tpb>>>(q, k, mask, s, KS, KS, KD,
                                (size_t)KS * KD, (size_t)KS * KD,
                                (size_t)KS * KS, (size_t)KS * KS);

    // Softmax over each of the 16384 rows
    softmax_kernel<<<KM, 256>>>(s);

    // Out = attn @ v_s : per batch M=2048, N=512, K=2048
    dim3 ga(KD / BN, KS / BM, KB);
    gemm_kernel<2><<<ga, tpb>>>(s, v, nullptr, out, KS, KD, KS,
                                (size_t)KS * KS, (size_t)KS * KD,
                                (size_t)KS * KD, 0);
}

// round 3
// speedup vs baseline: 2.3250x; 2.3250x over previous
#include <cuda_runtime.h>
#include <cuda_bf16.h>
#include <cstdint>
#include <math.h>

// ---------------- problem constants ----------------
#define KBATCH 8
#define KSEQ   2048
#define KDIM   512
#define KROWS  (KBATCH*KSEQ)   // 16384

// ---------------- scratch (device globals; no allocations) ----------------
__device__ float          g_q [(size_t)KROWS * KDIM];                 // q_s fp32
__device__ float          g_v [(size_t)KROWS * KDIM];                 // v_s fp32
__device__ __nv_bfloat16  g_ksh[(size_t)KROWS * KDIM];                // k_s hi  [S,D]=[N,K]
__device__ __nv_bfloat16  g_ksl[(size_t)KROWS * KDIM];                // k_s lo
__device__ __nv_bfloat16  g_vth[(size_t)KBATCH * KDIM * KSEQ];        // v_s^T hi [B][D][S]
__device__ __nv_bfloat16  g_vtl[(size_t)KBATCH * KDIM * KSEQ];        // v_s^T lo
__device__ float          g_s [(size_t)KBATCH * KSEQ * KSEQ];         // scores / probs
__device__ __nv_bfloat16  g_wh[3][(size_t)KDIM * KDIM];               // W^T hi [e][d]
__device__ __nv_bfloat16  g_wl[3][(size_t)KDIM * KDIM];               // W^T lo

// ---------------- helpers ----------------
__device__ __forceinline__ uint32_t smem_u32(const void* p) {
    uint32_t a;
    asm("{ .reg .u64 t; cvta.to.shared.u64 t, %1; cvt.u32.u64 %0, t; }" : "=r"(a) : "l"(p));
    return a;
}
__device__ __forceinline__ void split_f32(float x, __nv_bfloat16& h, __nv_bfloat16& l) {
    h = __float2bfloat16(x);
    l = __float2bfloat16(x - __bfloat162float(h));
}
__device__ __forceinline__ uint32_t pack2(__nv_bfloat16 a, __nv_bfloat16 b) {
    return (uint32_t)__bfloat16_as_ushort(a) | ((uint32_t)__bfloat16_as_ushort(b) << 16);
}
__device__ __forceinline__ void ldmx4(uint32_t& r0, uint32_t& r1, uint32_t& r2, uint32_t& r3,
                                      uint32_t addr) {
    asm volatile("ldmatrix.sync.aligned.m8n8.x4.shared.b16 {%0,%1,%2,%3}, [%4];"
                 : "=r"(r0), "=r"(r1), "=r"(r2), "=r"(r3) : "r"(addr));
}
__device__ __forceinline__ void mma_bf16(float* c, const uint32_t* a, uint32_t b0, uint32_t b1) {
    asm volatile("mma.sync.aligned.m16n8k16.row.col.f32.bf16.bf16.f32 "
                 "{%0,%1,%2,%3}, {%4,%5,%6,%7}, {%8,%9}, {%0,%1,%2,%3};"
                 : "+f"(c[0]), "+f"(c[1]), "+f"(c[2]), "+f"(c[3])
                 : "r"(a[0]), "r"(a[1]), "r"(a[2]), "r"(a[3]), "r"(b0), "r"(b1));
}

__device__ __forceinline__ float ssc() { return 0.044194173824159216f; } // 1/sqrt(512)

// ---------------- HMMA GEMM ----------------
// C[M,N] = A[M,K](f32, split in-kernel) * B^T, with B as bf16 hi/lo [N,K].
// EPI 0: +bias -> f32    EPI 1: *scale + mask -> f32
// EPI 2: plain -> f32    EPI 3: +bias -> split bf16 (Ch, Cl)
#define TILE_M 128
#define TILE_N 128
#define TILE_K 32
#define GT 256
#define PSTR 40                      // padded smem row stride (bf16 elements)
#define TILE_BYTES (128 * PSTR * 2)  // 10240 B per operand tile
// smem layout: stage s in {0,1}: [Ah][Al][Bh][Bl]
#define OFF_AH(s) ((s) * 4 * TILE_BYTES)
#define OFF_AL(s) (OFF_AH(s) + TILE_BYTES)
#define OFF_BH(s) (OFF_AH(s) + 2 * TILE_BYTES)
#define OFF_BL(s) (OFF_AH(s) + 3 * TILE_BYTES)
#define SMEM_BYTES (8 * TILE_BYTES)  // 81920

template<int EPI>
__global__ __launch_bounds__(GT)
void gemm_hmma(const float* __restrict__ A,
               const __nv_bfloat16* __restrict__ Bh,
               const __nv_bfloat16* __restrict__ Bl,
               const float* __restrict__ aux,
               float* __restrict__ C,
               __nv_bfloat16* __restrict__ Ch,
               __nv_bfloat16* __restrict__ Cl,
               int N, int K,
               size_t sA, size_t sB, size_t sC, size_t sAux)
{
    extern __shared__ char sm[];
    const uint32_t sb = smem_u32(sm);

    A   += sA   * (size_t)blockIdx.z;
    Bh  += sB   * (size_t)blockIdx.z;
    Bl  += sB   * (size_t)blockIdx.z;
    C   += sC   * (size_t)blockIdx.z;
    Ch  += sC   * (size_t)blockIdx.z;
    Cl  += sC   * (size_t)blockIdx.z;
    aux += sAux * (size_t)blockIdx.z;

    const int t    = threadIdx.x;
    const int lane = t & 31;
    const int w    = t >> 5;
    const int wm   = w & 3;         // warp row (4)
    const int wn   = w >> 2;        // warp col (2)
    const int bm   = blockIdx.y * TILE_M;
    const int bn   = blockIdx.x * TILE_N;

    // gmem load mappings
    const int arow = t >> 3;        // 0..31, 4 passes of +32
    const int ac4  = t & 7;         // float4 col within 32-K
    const int brow = t >> 2;        // 0..63, 2 passes of +64
    const int bc8  = t & 3;         // uint4 col within 32-K

    // ldmatrix address components
    const int a_r  = wm * 32 + (lane & 15);
    const int a_c8 = (lane >> 4) * 8;
    const int b_r  = wn * 64 + (lane & 7) + ((lane >> 4) & 1) * 8;
    const int b_c8 = ((lane >> 3) & 1) * 8;

    float acc[2][8][4];
    #pragma unroll
    for (int i = 0; i < 2; ++i)
        #pragma unroll
        for (int j = 0; j < 8; ++j)
            #pragma unroll
            for (int e = 0; e < 4; ++e) acc[i][j][e] = 0.0f;

    float4 pfA[4];
    uint4  pfBh[2], pfBl[2];

    const int nch = K / TILE_K;

    // prologue: load + store chunk 0
    {
        const int k0 = 0;
        #pragma unroll
        for (int p = 0; p < 4; ++p)
            pfA[p] = *reinterpret_cast<const float4*>(&A[(size_t)(bm + arow + p * 32) * K + k0 + ac4 * 4]);
        #pragma unroll
        for (int p = 0; p < 2; ++p) {
            const size_t gb = (size_t)(bn + brow + p * 64) * K + k0 + bc8 * 8;
            pfBh[p] = *reinterpret_cast<const uint4*>(&Bh[gb]);
            pfBl[p] = *reinterpret_cast<const uint4*>(&Bl[gb]);
        }
        #pragma unroll
        for (int p = 0; p < 4; ++p) {
            const int row = arow + p * 32;
            __nv_bfloat16 h0,h1,h2,h3,l0,l1,l2,l3;
            split_f32(pfA[p].x, h0, l0); split_f32(pfA[p].y, h1, l1);
            split_f32(pfA[p].z, h2, l2); split_f32(pfA[p].w, h3, l3);
            const uint32_t off = (uint32_t)(row * (PSTR * 2) + ac4 * 8);
            *reinterpret_cast<uint2*>(sm + OFF_AH(0) + off) = make_uint2(pack2(h0,h1), pack2(h2,h3));
            *reinterpret_cast<uint2*>(sm + OFF_AL(0) + off) = make_uint2(pack2(l0,l1), pack2(l2,l3));
        }
        #pragma unroll
        for (int p = 0; p < 2; ++p) {
            const int row = brow + p * 64;
            const uint32_t off = (uint32_t)(row * (PSTR * 2) + bc8 * 16);
            *reinterpret_cast<uint4*>(sm + OFF_BH(0) + off) = pfBh[p];
            *reinterpret_cast<uint4*>(sm + OFF_BL(0) + off) = pfBl[p];
        }
    }
    __syncthreads();

    for (int i = 0; i < nch; ++i) {
        const int s = i & 1;
        const bool hasNext = (i + 1) < nch;

        // issue gmem loads for next chunk (consumed after compute)
        if (hasNext) {
            const int k0 = (i + 1) * TILE_K;
            #pragma unroll
            for (int p = 0; p < 4; ++p)
                pfA[p] = *reinterpret_cast<const float4*>(&A[(size_t)(bm + arow + p * 32) * K + k0 + ac4 * 4]);
            #pragma unroll
            for (int p = 0; p < 2; ++p) {
                const size_t gb = (size_t)(bn + brow + p * 64) * K + k0 + bc8 * 8;
                pfBh[p] = *reinterpret_cast<const uint4*>(&Bh[gb]);
                pfBl[p] = *reinterpret_cast<const uint4*>(&Bl[gb]);
            }
        }

        // compute chunk i from stage s
        #pragma unroll
        for (int h = 0; h < 2; ++h) {
            const uint32_t acol = (uint32_t)((h * 16 + a_c8) * 2);
            uint32_t ah[2][4], al[2][4];
            #pragma unroll
            for (int mt = 0; mt < 2; ++mt) {
                const uint32_t aoff = (uint32_t)((a_r + mt * 16) * (PSTR * 2)) + acol;
                ldmx4(ah[mt][0], ah[mt][1], ah[mt][2], ah[mt][3], sb + OFF_AH(s) + aoff);
                ldmx4(al[mt][0], al[mt][1], al[mt][2], al[mt][3], sb + OFF_AL(s) + aoff);
            }
            const uint32_t bcol = (uint32_t)((h * 16 + b_c8) * 2);
            #pragma unroll
            for (int np = 0; np < 4; ++np) {
                const uint32_t boff = (uint32_t)((b_r + np * 16) * (PSTR * 2)) + bcol;
                uint32_t bh0, bh1, bh2, bh3, bl0, bl1, bl2, bl3;
                ldmx4(bh0, bh1, bh2, bh3, sb + OFF_BH(s) + boff);
                ldmx4(bl0, bl1, bl2, bl3, sb + OFF_BL(s) + boff);
                #pragma unroll
                for (int mt = 0; mt < 2; ++mt) {
                    mma_bf16(acc[mt][2*np],   ah[mt], bh0, bh1);
                    mma_bf16(acc[mt][2*np+1], ah[mt], bh2, bh3);
                    mma_bf16(acc[mt][2*np],   ah[mt], bl0, bl1);
                    mma_bf16(acc[mt][2*np+1], ah[mt], bl2, bl3);
                    mma_bf16(acc[mt][2*np],   al[mt], bh0, bh1);
                    mma_bf16(acc[mt][2*np+1], al[mt], bh2, bh3);
                }
            }
        }

        // store next chunk into the other stage (no sync needed before:
        // it targets the stage nobody reads this iteration)
        if (hasNext) {
            const int ns = s ^ 1;
            #pragma unroll
            for (int p = 0; p < 4; ++p) {
                const int row = arow + p * 32;
                __nv_bfloat16 h0,h1,h2,h3,l0,l1,l2,l3;
                split_f32(pfA[p].x, h0, l0); split_f32(pfA[p].y, h1, l1);
                split_f32(pfA[p].z, h2, l2); split_f32(pfA[p].w, h3, l3);
                const uint32_t off = (uint32_t)(row * (PSTR * 2) + ac4 * 8);
                *reinterpret_cast<uint2*>(sm + OFF_AH(ns) + off) = make_uint2(pack2(h0,h1), pack2(h2,h3));
                *reinterpret_cast<uint2*>(sm + OFF_AL(ns) + off) = make_uint2(pack2(l0,l1), pack2(l2,l3));
            }
            #pragma unroll
            for (int p = 0; p < 2; ++p) {
                const int row = brow + p * 64;
                const uint32_t off = (uint32_t)(row * (PSTR * 2) + bc8 * 16);
                *reinterpret_cast<uint4*>(sm + OFF_BH(ns) + off) = pfBh[p];
                *reinterpret_cast<uint4*>(sm + OFF_BL(ns) + off) = pfBl[p];
            }
        }
        __syncthreads();
    }

    // ---------------- epilogue ----------------
    const int er = (lane >> 2);        // 0..7
    const int ec = (lane & 3) * 2;     // 0..6
    #pragma unroll
    for (int mt = 0; mt < 2; ++mt) {
        #pragma unroll
        for (int nt = 0; nt < 8; ++nt) {
            const int col = bn + wn * 64 + nt * 8 + ec;
            #pragma unroll
            for (int half = 0; half < 2; ++half) {
                const int row = bm + wm * 32 + mt * 16 + er + half * 8;
                float x0 = acc[mt][nt][2*half + 0];
                float x1 = acc[mt][nt][2*half + 1];
                if (EPI == 0 || EPI == 3) {
                    x0 += aux[col];
                    x1 += aux[col + 1];
                }
                if (EPI == 1) {
                    const float2 m2 = *reinterpret_cast<const float2*>(&aux[(size_t)row * N + col]);
                    x0 = fmaf(x0, ssc(), m2.x);
                    x1 = fmaf(x1, ssc(), m2.y);
                }
                if (EPI == 3) {
                    __nv_bfloat16 h0,h1,l0,l1;
                    split_f32(x0, h0, l0);
                    split_f32(x1, h1, l1);
                    const size_t o = (size_t)row * N + col;
                    *reinterpret_cast<uint32_t*>(&Ch[o]) = pack2(h0, h1);
                    *reinterpret_cast<uint32_t*>(&Cl[o]) = pack2(l0, l1);
                } else {
                    *reinterpret_cast<float2*>(&C[(size_t)row * N + col]) = make_float2(x0, x1);
                }
            }
        }
    }
}

// ---------------- transpose + split: dst[c][r] = split(src[r][c]) ----------------
__global__ __launch_bounds__(256)
void transpose_split(const float* __restrict__ src,
                     __nv_bfloat16* __restrict__ dh,
                     __nv_bfloat16* __restrict__ dl,
                     int rows, int cols, size_t ss, size_t ds)
{
    __shared__ float tile[32][33];
    src += ss * (size_t)blockIdx.z;
    dh  += ds * (size_t)blockIdx.z;
    dl  += ds * (size_t)blockIdx.z;
    const int bx = blockIdx.x * 32;
    const int by = blockIdx.y * 32;
    const int tx = threadIdx.x & 31;
    const int ty = threadIdx.x >> 5;
    #pragma unroll
    for (int i = 0; i < 32; i += 8)
        tile[ty + i][tx] = src[(size_t)(by + ty + i) * cols + bx + tx];
    __syncthreads();
    #pragma unroll
    for (int i = 0; i < 32; i += 8) {
        float v = tile[tx][ty + i];
        __nv_bfloat16 h, l;
        split_f32(v, h, l);
        size_t o = (size_t)(bx + ty + i) * rows + by + tx;
        dh[o] = h; dl[o] = l;
    }
}

// ---------------- row softmax over 2048 ----------------
__global__ __launch_bounds__(256)
void softmax_kernel(float* __restrict__ S)
{
    __shared__ float buf[KSEQ];
    __shared__ float red[8];
    float* p = S + (size_t)blockIdx.x * KSEQ;
    const int t = threadIdx.x, lane = t & 31, wid = t >> 5;

    float mx = -3.4e38f;
    #pragma unroll
    for (int i = t; i < KSEQ; i += 256) { float v = p[i]; buf[i] = v; mx = fmaxf(mx, v); }
    #pragma unroll
    for (int o = 16; o > 0; o >>= 1) mx = fmaxf(mx, __shfl_xor_sync(0xffffffffu, mx, o));
    if (lane == 0) red[wid] = mx;
    __syncthreads();
    mx = fmaxf(fmaxf(fmaxf(red[0], red[1]), fmaxf(red[2], red[3])),
               fmaxf(fmaxf(red[4], red[5]), fmaxf(red[6], red[7])));
    __syncthreads();

    float sum = 0.0f;
    #pragma unroll
    for (int i = t; i < KSEQ; i += 256) { float e = __expf(buf[i] - mx); buf[i] = e; sum += e; }
    #pragma unroll
    for (int o = 16; o > 0; o >>= 1) sum += __shfl_xor_sync(0xffffffffu, sum, o);
    if (lane == 0) red[wid] = sum;
    __syncthreads();
    sum = ((red[0] + red[1]) + (red[2] + red[3])) + ((red[4] + red[5]) + (red[6] + red[7]));
    const float inv = 1.0f / sum;
    #pragma unroll
    for (int i = t; i < KSEQ; i += 256) p[i] = buf[i] * inv;
}

// ---------------- launch ----------------
extern "C" void kernel_launch(void* const* d_in, const int* in_sizes, int n_in,
                              void* d_out, int out_size)
{
    (void)in_sizes; (void)n_in; (void)out_size;
    const float* Q    = (const float*)d_in[0];
    const float* Kin  = (const float*)d_in[1];
    const float* Vin  = (const float*)d_in[2];
    const float* mask = (const float*)d_in[3];
    const float* Wq   = (const float*)d_in[4];
    const float* bq   = (const float*)d_in[5];
    const float* Wk   = (const float*)d_in[6];
    const float* bk   = (const float*)d_in[7];
    const float* Wv   = (const float*)d_in[8];
    const float* bv   = (const float*)d_in[9];
    float* out = (float*)d_out;

    float *q, *v, *s;
    __nv_bfloat16 *ksh, *ksl, *vth, *vtl, *wh, *wl;
    cudaGetSymbolAddress((void**)&q,   g_q);
    cudaGetSymbolAddress((void**)&v,   g_v);
    cudaGetSymbolAddress((void**)&s,   g_s);
    cudaGetSymbolAddress((void**)&ksh, g_ksh);
    cudaGetSymbolAddress((void**)&ksl, g_ksl);
    cudaGetSymbolAddress((void**)&vth, g_vth);
    cudaGetSymbolAddress((void**)&vtl, g_vtl);
    cudaGetSymbolAddress((void**)&wh,  g_wh);
    cudaGetSymbolAddress((void**)&wl,  g_wl);

    cudaFuncSetAttribute(gemm_hmma<0>, cudaFuncAttributeMaxDynamicSharedMemorySize, SMEM_BYTES);
    cudaFuncSetAttribute(gemm_hmma<1>, cudaFuncAttributeMaxDynamicSharedMemorySize, SMEM_BYTES);
    cudaFuncSetAttribute(gemm_hmma<2>, cudaFuncAttributeMaxDynamicSharedMemorySize, SMEM_BYTES);
    cudaFuncSetAttribute(gemm_hmma<3>, cudaFuncAttributeMaxDynamicSharedMemorySize, SMEM_BYTES);

    const size_t WSZ = (size_t)KDIM * KDIM;
    dim3 tb(256);

    // 1) transpose + split weights -> [e][d] bf16 hi/lo
    transpose_split<<<dim3(16, 16, 1), tb>>>(Wq, wh + 0*WSZ, wl + 0*WSZ, KDIM, KDIM, 0, 0);
    transpose_split<<<dim3(16, 16, 1), tb>>>(Wk, wh + 1*WSZ, wl + 1*WSZ, KDIM, KDIM, 0, 0);
    transpose_split<<<dim3(16, 16, 1), tb>>>(Wv, wh + 2*WSZ, wl + 2*WSZ, KDIM, KDIM, 0, 0);

    // 2) projections (M=16384, N=512, K=512)
    dim3 gp(KDIM / TILE_N, KROWS / TILE_M, 1);
    gemm_hmma<0><<<gp, GT, SMEM_BYTES>>>(Q,   wh + 0*WSZ, wl + 0*WSZ, bq, q, nullptr, nullptr,
                                         KDIM, KDIM, 0, 0, 0, 0);
    gemm_hmma<3><<<gp, GT, SMEM_BYTES>>>(Kin, wh + 1*WSZ, wl + 1*WSZ, bk, nullptr, ksh, ksl,
                                         KDIM, KDIM, 0, 0, 0, 0);
    gemm_hmma<0><<<gp, GT, SMEM_BYTES>>>(Vin, wh + 2*WSZ, wl + 2*WSZ, bv, v, nullptr, nullptr,
                                         KDIM, KDIM, 0, 0, 0, 0);

    // 3) v_s -> v_s^T split  [B][D][S]
    transpose_split<<<dim3(KDIM / 32, KSEQ / 32, KBATCH), tb>>>(
        v, vth, vtl, KSEQ, KDIM, (size_t)KSEQ * KDIM, (size_t)KDIM * KSEQ);

    // 4) scores = q_s k_s^T * scale + mask   (per batch 2048x2048, K=512)
    dim3 gs(KSEQ / TILE_N, KSEQ / TILE_M, KBATCH);
    gemm_hmma<1><<<gs, GT, SMEM_BYTES>>>(q, ksh, ksl, mask, s, nullptr, nullptr,
                                         KSEQ, KDIM,
                                         (size_t)KSEQ * KDIM, (size_t)KSEQ * KDIM,
                                         (size_t)KSEQ * KSEQ, (size_t)KSEQ * KSEQ);

    // 5) softmax
    softmax_kernel<<<KROWS, 256>>>(s);

    // 6) out = probs @ v_s   (per batch 2048x512, K=2048)
    dim3 ga(KDIM / TILE_N, KSEQ / TILE_M, KBATCH);
    gemm_hmma<2><<<ga, GT, SMEM_BYTES>>>(s, vth, vtl, nullptr, out, nullptr, nullptr,
                                         KDIM, KSEQ,
                                         (size_t)KSEQ * KSEQ, (size_t)KDIM * KSEQ,
                                         (size_t)KSEQ * KDIM, 0);
}